// round 11
// baseline (speedup 1.0000x reference)
#include <cuda_runtime.h>
#include <cuda_bf16.h>

// B=524288, D=256, C=1000 (D hardcoded for thread-per-element layout).
#define D_DIM 256
#define C_MAX 1024
#define BUCKET_CAP 2048     // expected ~524/class, Poisson max ~650
#define CNT_PAD 32          // one counter per 128B line -> distinct LTS slices
#define BIN_CHUNK 4096      // labels per bin block (128 blocks: proven optimum)

// Scratch: __device__ globals (zero-initialized at load; self-cleaned per run).
__device__ int   g_counts[C_MAX * CNT_PAD];   // padded counters (128 KB)
__device__ int   g_bucket[C_MAX * BUCKET_CAP];
__device__ float g_loss_sum;
__device__ int   g_n_present;
__device__ int   g_done;

// ---------------------------------------------------------------------------
// Kernel 1: two-level binning (R10 config, proven). Ends with a PDL trigger
// so the dependent class grid can be scheduled while this grid drains.
// ---------------------------------------------------------------------------
__global__ void __launch_bounds__(1024) bin_kernel(const void* __restrict__ lraw,
                                                   int B, int C) {
    __shared__ unsigned short s_lab[BIN_CHUNK];   // 8 KB
    __shared__ int s_hist[C_MAX];                 // 4 KB (hist, then cursor)
    __shared__ int s_base[C_MAX];                 // 4 KB
    __shared__ int s_bad;

    const int tid = threadIdx.x;
    if (tid == 0) s_bad = 0;
    for (int i = tid; i < C_MAX; i += 1024) s_hist[i] = 0;
    __syncthreads();

    const long long* __restrict__ l64 = (const long long*)lraw;
    const int* __restrict__       l32 = (const int*)lraw;

    {
        const int n = (B < 1024) ? B : 1024;
        int bad = 0;
        for (int i = tid; i < n; i += 1024) {
            const long long v = l64[i];
            if (v < 0 || v >= (long long)C) bad = 1;
        }
        if (bad) atomicOr(&s_bad, 1);
    }
    __syncthreads();
    const bool is64 = (s_bad == 0);

    const int start = blockIdx.x * BIN_CHUNK;
    const int end   = (start + BIN_CHUNK < B) ? (start + BIN_CHUNK) : B;
    const int cnt   = end - start;

    // Phase A: decode + local histogram
    for (int i = tid; i < cnt; i += 1024) {
        const int c = is64 ? (int)l64[start + i] : l32[start + i];
        s_lab[i] = (unsigned short)c;
        atomicAdd(&s_hist[c], 1);
    }
    __syncthreads();

    // Phase B: reserve global ranges (staggered start per block);
    // reset hist for reuse as cursor.
    {
        const int off = (blockIdx.x * 19) % C;
        for (int k = tid; k < C; k += 1024) {
            int c = k + off;
            if (c >= C) c -= C;
            const int h = s_hist[c];
            s_base[c] = h ? atomicAdd(&g_counts[c * CNT_PAD], h) : 0;
            s_hist[c] = 0;
        }
    }
    __syncthreads();

    // Phase C: scatter row indices into reserved (contiguous) slots
    for (int i = tid; i < cnt; i += 1024) {
        const int c   = s_lab[i];
        const int pos = s_base[c] + atomicAdd(&s_hist[c], 1);
        if (pos < BUCKET_CAP) g_bucket[c * BUCKET_CAP + pos] = start + i;
    }

    // PDL: allow the dependent class grid to launch/schedule now. Memory
    // visibility for its reads is still guaranteed by its grid-dependency
    // sync (waits for THIS grid's completion), so an early trigger is safe.
    cudaTriggerProgrammaticLaunchCompletion();
}

// ---------------------------------------------------------------------------
// Block reduce over 256 threads (8 warps)
// ---------------------------------------------------------------------------
__device__ __forceinline__ float block_reduce_256(float v, float* s_red, int tid) {
    #pragma unroll
    for (int o = 16; o > 0; o >>= 1) v += __shfl_down_sync(0xffffffffu, v, o);
    if ((tid & 31) == 0) s_red[tid >> 5] = v;
    __syncthreads();
    if (tid < 32) {
        v = (tid < 8) ? s_red[tid] : 0.0f;
        #pragma unroll
        for (int o = 4; o > 0; o >>= 1) v += __shfl_down_sync(0xffffffffu, v, o);
        if (tid == 0) s_red[0] = v;
    }
    __syncthreads();
    const float r = s_red[0];
    __syncthreads();
    return r;
}

// ---------------------------------------------------------------------------
// Kernel 2: R5/R10 class kernel (measured optimum: 32 regs, 8 blocks/SM,
// ~88.6us @ 75% DRAM — the pattern ceiling), now launched via PDL. The only
// addition is the grid-dependency sync before the first dependent read.
// ---------------------------------------------------------------------------
__global__ void __launch_bounds__(256) class_kernel(
    const float* __restrict__ x,
    const float* __restrict__ cimg,
    const float* __restrict__ cskt,
    float* __restrict__ out)
{
    // Wait for bin_kernel grid completion (PDL). All its writes are visible
    // after this returns.
    cudaGridDependencySynchronize();

    const int c   = blockIdx.x;
    const int tid = threadIdx.x;
    const int q   = tid >> 6;        // row slot 0..3
    const int ds  = tid & 63;        // float4 index within a 256-float row

    __shared__ __align__(16) float s_part[4 * 256];
    __shared__ __align__(16) int   s_rows[512];
    __shared__ float s_red[32];
    __shared__ int   s_count;

    if (tid == 0) {
        s_count = g_counts[c * CNT_PAD];
        g_counts[c * CNT_PAD] = 0;   // self-clean for next graph replay
    }
    __syncthreads();
    const int count = s_count;

    if (count > 0) {
        const int m = (count < BUCKET_CAP) ? count : BUCKET_CAP;
        const int* __restrict__ bucket = &g_bucket[c * BUCKET_CAP];

        float4 acc = make_float4(0.f, 0.f, 0.f, 0.f);

        for (int base = 0; base < m; base += 512) {
            const int seg = (m - base < 512) ? (m - base) : 512;
            __syncthreads();
            for (int t = tid; t < seg; t += 256) s_rows[t] = bucket[base + t];
            __syncthreads();

            int j = 0;
            for (; j + 16 <= seg; j += 16) {
                const int r0 = s_rows[j      + q];
                const int r1 = s_rows[j + 4  + q];
                const int r2 = s_rows[j + 8  + q];
                const int r3 = s_rows[j + 12 + q];
                const float4 v0 = __ldg((const float4*)(x + (size_t)r0 * D_DIM) + ds);
                const float4 v1 = __ldg((const float4*)(x + (size_t)r1 * D_DIM) + ds);
                const float4 v2 = __ldg((const float4*)(x + (size_t)r2 * D_DIM) + ds);
                const float4 v3 = __ldg((const float4*)(x + (size_t)r3 * D_DIM) + ds);
                acc.x += v0.x + v1.x + v2.x + v3.x;
                acc.y += v0.y + v1.y + v2.y + v3.y;
                acc.z += v0.z + v1.z + v2.z + v3.z;
                acc.w += v0.w + v1.w + v2.w + v3.w;
            }
            for (; j < seg; j += 4) {
                const int idx = j + q;
                if (idx < seg) {
                    const int r = s_rows[idx];
                    const float4 v = __ldg((const float4*)(x + (size_t)r * D_DIM) + ds);
                    acc.x += v.x; acc.y += v.y; acc.z += v.z; acc.w += v.w;
                }
            }
        }

        // Combine the 4 row-slot partial sums across q via smem.
        __syncthreads();
        *((float4*)(s_part + q * 256) + ds) = acc;
        __syncthreads();
        const float sum = s_part[0 * 256 + tid] + s_part[1 * 256 + tid] +
                          s_part[2 * 256 + tid] + s_part[3 * 256 + tid];

        const float mean = sum / (float)count;
        const float ci   = cimg[c * D_DIM + tid];
        const float upd  = fmaf(ci, 0.9f, mean * 0.1f);

        const float nrm2 = block_reduce_256(upd * upd, s_red, tid);
        const float v    = upd * rsqrtf(nrm2);

        const float d  = v - cskt[c * D_DIM + tid];
        const float sq = block_reduce_256(d * d, s_red, tid);

        if (tid == 0) {
            atomicAdd(&g_loss_sum, sq);
            atomicAdd(&g_n_present, 1);
        }
    }

    // Completion protocol: last block finalizes the scalar and resets scratch.
    if (tid == 0) {
        __threadfence();
        const int t = atomicAdd(&g_done, 1);
        if (t == (int)gridDim.x - 1) {
            const float ls = atomicAdd(&g_loss_sum, 0.0f);   // coherent read
            int np = atomicAdd(&g_n_present, 0);
            if (np < 1) np = 1;
            out[0] = ls / (float)np;
            g_loss_sum  = 0.0f;
            g_n_present = 0;
            g_done      = 0;
        }
    }
}

// ---------------------------------------------------------------------------
extern "C" void kernel_launch(void* const* d_in, const int* in_sizes, int n_in,
                              void* d_out, int out_size) {
    const float* x    = (const float*)d_in[0];
    const void*  lraw = d_in[1];
    const float* cimg = (const float*)d_in[2];
    const float* cskt = (const float*)d_in[3];
    float* out = (float*)d_out;

    const int B = in_sizes[1];           // 524288
    const int C = in_sizes[2] / D_DIM;   // 1000

    const int nb = (B + BIN_CHUNK - 1) / BIN_CHUNK;   // 128
    bin_kernel<<<nb, 1024>>>(lraw, B, C);

    // PDL launch: class_kernel may be scheduled while bin_kernel drains;
    // its cudaGridDependencySynchronize() enforces the data dependency.
    cudaLaunchConfig_t cfg = {};
    cfg.gridDim  = dim3((unsigned)C, 1, 1);
    cfg.blockDim = dim3(256, 1, 1);
    cfg.dynamicSmemBytes = 0;
    cudaLaunchAttribute attrs[1];
    attrs[0].id = cudaLaunchAttributeProgrammaticStreamSerialization;
    attrs[0].val.programmaticStreamSerializationAllowed = 1;
    cfg.attrs = attrs;
    cfg.numAttrs = 1;
    cudaLaunchKernelEx(&cfg, class_kernel, x, cimg, cskt, out);
}

// round 12
// speedup vs baseline: 1.0013x; 1.0013x over previous
#include <cuda_runtime.h>
#include <cuda_bf16.h>

// B=524288, D=256, C=1000 (D hardcoded for thread-per-element layout).
#define D_DIM 256
#define C_MAX 1024
#define BUCKET_CAP 2048     // expected ~524/class, Poisson max ~650
#define CNT_PAD 32          // one counter per 128B line -> distinct LTS slices
#define BIN_CHUNK 4096      // labels per bin block (128 blocks: proven optimum)
#define CLASS_GRID 1184     // 148 SMs x 8 resident blocks (persistent, stealing)

// Scratch: __device__ globals (zero-initialized at load; self-cleaned per run).
__device__ int   g_counts[C_MAX * CNT_PAD];   // padded counters (128 KB)
__device__ int   g_bucket[C_MAX * BUCKET_CAP];
__device__ float g_loss_sum;
__device__ int   g_n_present;
__device__ int   g_done;
__device__ int   g_ticket;

// ---------------------------------------------------------------------------
// Kernel 1: two-level binning (proven R10 config).
// ---------------------------------------------------------------------------
__global__ void __launch_bounds__(1024) bin_kernel(const void* __restrict__ lraw,
                                                   int B, int C) {
    __shared__ unsigned short s_lab[BIN_CHUNK];   // 8 KB
    __shared__ int s_hist[C_MAX];                 // 4 KB (hist, then cursor)
    __shared__ int s_base[C_MAX];                 // 4 KB
    __shared__ int s_bad;

    const int tid = threadIdx.x;
    if (tid == 0) s_bad = 0;
    for (int i = tid; i < C_MAX; i += 1024) s_hist[i] = 0;
    __syncthreads();

    const long long* __restrict__ l64 = (const long long*)lraw;
    const int* __restrict__       l32 = (const int*)lraw;

    {
        const int n = (B < 1024) ? B : 1024;
        int bad = 0;
        for (int i = tid; i < n; i += 1024) {
            const long long v = l64[i];
            if (v < 0 || v >= (long long)C) bad = 1;
        }
        if (bad) atomicOr(&s_bad, 1);
    }
    __syncthreads();
    const bool is64 = (s_bad == 0);

    const int start = blockIdx.x * BIN_CHUNK;
    const int end   = (start + BIN_CHUNK < B) ? (start + BIN_CHUNK) : B;
    const int cnt   = end - start;

    // Phase A: decode + local histogram
    for (int i = tid; i < cnt; i += 1024) {
        const int c = is64 ? (int)l64[start + i] : l32[start + i];
        s_lab[i] = (unsigned short)c;
        atomicAdd(&s_hist[c], 1);
    }
    __syncthreads();

    // Phase B: reserve global ranges (staggered start per block);
    // reset hist for reuse as cursor.
    {
        const int off = (blockIdx.x * 19) % C;
        for (int k = tid; k < C; k += 1024) {
            int c = k + off;
            if (c >= C) c -= C;
            const int h = s_hist[c];
            s_base[c] = h ? atomicAdd(&g_counts[c * CNT_PAD], h) : 0;
            s_hist[c] = 0;
        }
    }
    __syncthreads();

    // Phase C: scatter row indices into reserved (contiguous) slots
    for (int i = tid; i < cnt; i += 1024) {
        const int c   = s_lab[i];
        const int pos = s_base[c] + atomicAdd(&s_hist[c], 1);
        if (pos < BUCKET_CAP) g_bucket[c * BUCKET_CAP + pos] = start + i;
    }
}

// ---------------------------------------------------------------------------
// Block reduce over 256 threads (8 warps)
// ---------------------------------------------------------------------------
__device__ __forceinline__ float block_reduce_256(float v, float* s_red, int tid) {
    #pragma unroll
    for (int o = 16; o > 0; o >>= 1) v += __shfl_down_sync(0xffffffffu, v, o);
    if ((tid & 31) == 0) s_red[tid >> 5] = v;
    __syncthreads();
    if (tid < 32) {
        v = (tid < 8) ? s_red[tid] : 0.0f;
        #pragma unroll
        for (int o = 4; o > 0; o >>= 1) v += __shfl_down_sync(0xffffffffu, v, o);
        if (tid == 0) s_red[0] = v;
    }
    __syncthreads();
    const float r = s_red[0];
    __syncthreads();
    return r;
}

// ---------------------------------------------------------------------------
// Kernel 2: persistent work-stealing class processor. 1184 blocks (one per
// resident slot) pull classes from a global ticket counter: perfect load
// balance + 100% slot occupancy vs the static 1000-block grid's 84%.
// Per-class body identical to the proven R5/R10 kernel.
// ---------------------------------------------------------------------------
__global__ void __launch_bounds__(256, 8) class_kernel(
    const float* __restrict__ x,
    const float* __restrict__ cimg,
    const float* __restrict__ cskt,
    float* __restrict__ out,
    int C)
{
    const int tid = threadIdx.x;
    const int q   = tid >> 6;        // row slot 0..3
    const int ds  = tid & 63;        // float4 index within a 256-float row

    __shared__ __align__(16) float s_part[4 * 256];
    __shared__ __align__(16) int   s_rows[512];
    __shared__ float s_red[32];
    __shared__ int   s_count, s_c;

    for (;;) {
        if (tid == 0) s_c = atomicAdd(&g_ticket, 1);
        __syncthreads();
        const int c = s_c;
        if (c >= C) break;

        if (tid == 0) {
            s_count = g_counts[c * CNT_PAD];
            g_counts[c * CNT_PAD] = 0;   // self-clean for next graph replay
        }
        __syncthreads();
        const int count = s_count;

        if (count > 0) {
            const int m = (count < BUCKET_CAP) ? count : BUCKET_CAP;
            const int* __restrict__ bucket = &g_bucket[c * BUCKET_CAP];

            float4 acc = make_float4(0.f, 0.f, 0.f, 0.f);

            for (int base = 0; base < m; base += 512) {
                const int seg = (m - base < 512) ? (m - base) : 512;
                __syncthreads();
                for (int t = tid; t < seg; t += 256) s_rows[t] = bucket[base + t];
                __syncthreads();

                int j = 0;
                for (; j + 16 <= seg; j += 16) {
                    const int r0 = s_rows[j      + q];
                    const int r1 = s_rows[j + 4  + q];
                    const int r2 = s_rows[j + 8  + q];
                    const int r3 = s_rows[j + 12 + q];
                    const float4 v0 = __ldg((const float4*)(x + (size_t)r0 * D_DIM) + ds);
                    const float4 v1 = __ldg((const float4*)(x + (size_t)r1 * D_DIM) + ds);
                    const float4 v2 = __ldg((const float4*)(x + (size_t)r2 * D_DIM) + ds);
                    const float4 v3 = __ldg((const float4*)(x + (size_t)r3 * D_DIM) + ds);
                    acc.x += v0.x + v1.x + v2.x + v3.x;
                    acc.y += v0.y + v1.y + v2.y + v3.y;
                    acc.z += v0.z + v1.z + v2.z + v3.z;
                    acc.w += v0.w + v1.w + v2.w + v3.w;
                }
                for (; j < seg; j += 4) {
                    const int idx = j + q;
                    if (idx < seg) {
                        const int r = s_rows[idx];
                        const float4 v = __ldg((const float4*)(x + (size_t)r * D_DIM) + ds);
                        acc.x += v.x; acc.y += v.y; acc.z += v.z; acc.w += v.w;
                    }
                }
            }

            // Combine the 4 row-slot partial sums across q via smem.
            __syncthreads();
            *((float4*)(s_part + q * 256) + ds) = acc;
            __syncthreads();
            const float sum = s_part[0 * 256 + tid] + s_part[1 * 256 + tid] +
                              s_part[2 * 256 + tid] + s_part[3 * 256 + tid];

            const float mean = sum / (float)count;
            const float ci   = cimg[c * D_DIM + tid];
            const float upd  = fmaf(ci, 0.9f, mean * 0.1f);

            const float nrm2 = block_reduce_256(upd * upd, s_red, tid);
            const float v    = upd * rsqrtf(nrm2);

            const float d  = v - cskt[c * D_DIM + tid];
            const float sq = block_reduce_256(d * d, s_red, tid);

            if (tid == 0) {
                atomicAdd(&g_loss_sum, sq);
                atomicAdd(&g_n_present, 1);
            }
        }
        __syncthreads();   // protect s_c/s_count before next iteration's writes
    }

    // Completion protocol: last finishing block writes scalar + resets scratch.
    if (tid == 0) {
        __threadfence();
        const int t = atomicAdd(&g_done, 1);
        if (t == (int)gridDim.x - 1) {
            const float ls = atomicAdd(&g_loss_sum, 0.0f);   // coherent read
            int np = atomicAdd(&g_n_present, 0);
            if (np < 1) np = 1;
            out[0] = ls / (float)np;
            g_loss_sum  = 0.0f;
            g_n_present = 0;
            g_done      = 0;
            g_ticket    = 0;
        }
    }
}

// ---------------------------------------------------------------------------
extern "C" void kernel_launch(void* const* d_in, const int* in_sizes, int n_in,
                              void* d_out, int out_size) {
    const float* x    = (const float*)d_in[0];
    const void*  lraw = d_in[1];
    const float* cimg = (const float*)d_in[2];
    const float* cskt = (const float*)d_in[3];
    float* out = (float*)d_out;

    const int B = in_sizes[1];           // 524288
    const int C = in_sizes[2] / D_DIM;   // 1000

    const int nb = (B + BIN_CHUNK - 1) / BIN_CHUNK;   // 128
    bin_kernel<<<nb, 1024>>>(lraw, B, C);
    class_kernel<<<CLASS_GRID, 256>>>(x, cimg, cskt, out, C);
}